// round 13
// baseline (speedup 1.0000x reference)
#include <cuda_runtime.h>
#include <math.h>

// Problem constants
#define B_ 512
#define T_ 2048
#define H_ 128
#define E_ 256
#define V_ 34

// Output layout: (out[B,V], c[B,H], sh0[B,H], sh1[B,H], sc0[B,H], sc1[B,H], atten_vec[T])
#define OFF_OUT 0
#define OFF_C   (B_*V_)
#define OFF_SH0 (OFF_C   + B_*H_)
#define OFF_SH1 (OFF_SH0 + B_*H_)
#define OFF_SC0 (OFF_SH1 + B_*H_)
#define OFF_SC1 (OFF_SC0 + B_*H_)
#define OFF_ATT (OFF_SC1 + B_*H_)

// Scratch (__device__ globals; no allocations allowed)
__device__ float g_pre[B_*H_];    // head pre-BN output
__device__ float g_bnacc[2*H_];   // [0:128) sum, [128:256) sum of squares

__device__ __forceinline__ float sigm(float x) { return 1.f / (1.f + __expf(-x)); }

// ---------------------------------------------------------------------------
// LSTM cell with in-block split-K on the proven 32-row tile.
// zero_acc != 0: block (0,0)'s idle worker-1 threads zero g_bnacc during the
// epilogue (stream order puts this before k_attn's atomics).
// ---------------------------------------------------------------------------
struct GemmBuf32 { float Xs[2][16][34]; float Ws[2][16][68]; };

__global__ void __launch_bounds__(512) k_lstm(
    const float* __restrict__ A, int ka,
    const float* __restrict__ Bp, int kb,
    const float* __restrict__ Cp, int kc,
    const float* __restrict__ Wih, int Kin,
    const float* __restrict__ Whh,
    const float* __restrict__ bih, const float* __restrict__ bhh,
    const float* __restrict__ c_prev,
    float* __restrict__ h_out, float* __restrict__ c_out,
    int zero_acc)
{
    __shared__ GemmBuf32 gbuf[2];
    __shared__ float comb[256][8];
    const int tid = threadIdx.x;
    const int widx = tid >> 8;          // worker 0/1
    const int wtid = tid & 255;
    GemmBuf32& g = gbuf[widx];
    const int tx = wtid & 15, ty = wtid >> 4;
    const int m0 = blockIdx.y * 32;
    const int h0 = blockIdx.x * 16;
    const int lkk = wtid & 15, lr = wtid >> 4;

    const int K = ka + kb + kc;
    const int halfK = K >> 1;
    const int nt = halfK >> 4;
    const int kofs = widx * halfK;

    int wn[4];
    #pragma unroll
    for (int p = 0; p < 4; p++) {
        int c = lr + p * 16;
        wn[p] = (c & 3) * H_ + h0 + (c >> 2);   // gate*H + h
    }

    {
        int k = kofs + lkk;
        float x0, x1;
        if (k < ka)           { x0 = A[(m0+lr)*ka + k];            x1 = A[(m0+lr+16)*ka + k]; }
        else if (k < ka + kb) { x0 = Bp[(m0+lr)*kb + k - ka];      x1 = Bp[(m0+lr+16)*kb + k - ka]; }
        else                  { x0 = Cp[(m0+lr)*kc + k - ka - kb]; x1 = Cp[(m0+lr+16)*kc + k - ka - kb]; }
        g.Xs[0][lkk][lr] = x0; g.Xs[0][lkk][lr+16] = x1;
        #pragma unroll
        for (int p = 0; p < 4; p++)
            g.Ws[0][lkk][lr + p*16] = (k < Kin) ? Wih[wn[p]*Kin + k] : Whh[wn[p]*H_ + k - Kin];
    }
    __syncthreads();

    float acc[2][4] = {};
    for (int it = 0; it < nt; it++) {
        const int cur = it & 1, nxt = cur ^ 1;
        float px0 = 0.f, px1 = 0.f, pw[4] = {0.f,0.f,0.f,0.f};
        const bool more = (it + 1 < nt);
        if (more) {
            int k = kofs + (it + 1) * 16 + lkk;
            if (k < ka)           { px0 = A[(m0+lr)*ka + k];            px1 = A[(m0+lr+16)*ka + k]; }
            else if (k < ka + kb) { px0 = Bp[(m0+lr)*kb + k - ka];      px1 = Bp[(m0+lr+16)*kb + k - ka]; }
            else                  { px0 = Cp[(m0+lr)*kc + k - ka - kb]; px1 = Cp[(m0+lr+16)*kc + k - ka - kb]; }
            #pragma unroll
            for (int p = 0; p < 4; p++)
                pw[p] = (k < Kin) ? Wih[wn[p]*Kin + k] : Whh[wn[p]*H_ + k - Kin];
        }
        #pragma unroll
        for (int kk = 0; kk < 16; kk++) {
            float x0 = g.Xs[cur][kk][ty*2];
            float x1 = g.Xs[cur][kk][ty*2 + 1];
            float4 wv = *(const float4*)&g.Ws[cur][kk][tx*4];
            acc[0][0] = fmaf(x0, wv.x, acc[0][0]);
            acc[0][1] = fmaf(x0, wv.y, acc[0][1]);
            acc[0][2] = fmaf(x0, wv.z, acc[0][2]);
            acc[0][3] = fmaf(x0, wv.w, acc[0][3]);
            acc[1][0] = fmaf(x1, wv.x, acc[1][0]);
            acc[1][1] = fmaf(x1, wv.y, acc[1][1]);
            acc[1][2] = fmaf(x1, wv.z, acc[1][2]);
            acc[1][3] = fmaf(x1, wv.w, acc[1][3]);
        }
        if (more) {
            g.Xs[nxt][lkk][lr] = px0;
            g.Xs[nxt][lkk][lr+16] = px1;
            #pragma unroll
            for (int p = 0; p < 4; p++) g.Ws[nxt][lkk][lr + p*16] = pw[p];
            __syncthreads();
        }
    }

    if (widx == 1) {
        #pragma unroll
        for (int r = 0; r < 2; r++)
            #pragma unroll
            for (int j = 0; j < 4; j++) comb[wtid][r*4 + j] = acc[r][j];
    }
    __syncthreads();
    if (widx == 0) {
        const int h = h0 + tx;
        const float bi = bih[h]         + bhh[h];
        const float bf = bih[H_ + h]    + bhh[H_ + h];
        const float bg = bih[2*H_ + h]  + bhh[2*H_ + h];
        const float bo = bih[3*H_ + h]  + bhh[3*H_ + h];
        #pragma unroll
        for (int r = 0; r < 2; r++) {
            const int m = m0 + ty*2 + r;
            float a0 = acc[r][0] + comb[wtid][r*4 + 0];
            float a1 = acc[r][1] + comb[wtid][r*4 + 1];
            float a2 = acc[r][2] + comb[wtid][r*4 + 2];
            float a3 = acc[r][3] + comb[wtid][r*4 + 3];
            float ig = sigm(a0 + bi);
            float fg = sigm(a1 + bf);
            float gg = tanhf(a2 + bg);
            float og = sigm(a3 + bo);
            float cn = fg * c_prev[m*H_ + h] + ig * gg;
            c_out[m*H_ + h] = cn;
            h_out[m*H_ + h] = og * tanhf(cn);
        }
    } else if (zero_acc && blockIdx.x == 0 && blockIdx.y == 0) {
        g_bnacc[wtid] = 0.f;            // 256 floats, one per worker-1 thread
    }
}

// ---------------------------------------------------------------------------
// Fused attention + head + BN-stat atomics. 256-thread blocks (8 warps),
// 4 resident/SM. One block per batch row; hk/hv streamed once.
// ---------------------------------------------------------------------------
__global__ void __launch_bounds__(256, 4) k_attn(
    const float* __restrict__ hk, const float* __restrict__ hv,
    const float* __restrict__ q, const float* __restrict__ mask,
    const float* __restrict__ W1, const float* __restrict__ W2,
    const float* __restrict__ b1, const float* __restrict__ b2,
    float* __restrict__ c_out, float* __restrict__ att0)
{
    __shared__ float  sa[T_];
    __shared__ float4 sq[32];           // q row
    __shared__ float4 cc[32];           // c row
    __shared__ float4 part[8][32];
    __shared__ float  red[8];
    const int b = blockIdx.x, tid = threadIdx.x;
    const int warp = tid >> 5, lane = tid & 31;

    if (tid < 32) sq[tid] = ((const float4*)(q + (size_t)b * H_))[tid];
    __syncthreads();
    const float4 qv = sq[lane];

    // ---- Phase 1: scores. Warp w covers t in [w*256,(w+1)*256), MLP=8.
    const float4* kbase = (const float4*)(hk + (size_t)b * (T_ * H_));
    {
        const int tbeg = warp * 256;
        for (int t0 = tbeg; t0 < tbeg + 256; t0 += 8) {
            float4 v[8];
            #pragma unroll
            for (int j = 0; j < 8; j++)
                v[j] = __ldcs(&kbase[(size_t)(t0+j) * 32 + lane]);
            float d[8];
            #pragma unroll
            for (int j = 0; j < 8; j++)
                d[j] = v[j].x*qv.x + v[j].y*qv.y + v[j].z*qv.z + v[j].w*qv.w;
            #pragma unroll
            for (int st = 16; st > 0; st >>= 1) {
                #pragma unroll
                for (int j = 0; j < 8; j++)
                    d[j] += __shfl_xor_sync(0xffffffffu, d[j], st);
            }
            if (lane == 0) {
                #pragma unroll
                for (int j = 0; j < 8; j++) sa[t0+j] = d[j];
            }
        }
    }
    __syncthreads();

    // ---- Phase 2: masked renormalized softmax (smem-resident, low regs).
    {
        const float* mk = mask + (size_t)b * T_;
        float mx = -1e30f;
        #pragma unroll
        for (int i = 0; i < 8; i++) mx = fmaxf(mx, sa[tid + i*256]);
        #pragma unroll
        for (int st = 16; st > 0; st >>= 1)
            mx = fmaxf(mx, __shfl_xor_sync(0xffffffffu, mx, st));
        if (lane == 0) red[warp] = mx;
        __syncthreads();
        if (warp == 0) {
            float m2 = (lane < 8) ? red[lane] : -1e30f;
            #pragma unroll
            for (int st = 4; st > 0; st >>= 1)
                m2 = fmaxf(m2, __shfl_xor_sync(0xffffffffu, m2, st));
            if (lane == 0) red[0] = m2;
        }
        __syncthreads();
        mx = red[0];
        __syncthreads();

        float sum = 0.f;
        #pragma unroll
        for (int i = 0; i < 8; i++) {
            float e = __expf(sa[tid + i*256] - mx) * mk[tid + i*256];
            sa[tid + i*256] = e;
            sum += e;
        }
        #pragma unroll
        for (int st = 16; st > 0; st >>= 1)
            sum += __shfl_xor_sync(0xffffffffu, sum, st);
        if (lane == 0) red[warp] = sum;
        __syncthreads();
        if (warp == 0) {
            float s2 = (lane < 8) ? red[lane] : 0.f;
            #pragma unroll
            for (int st = 4; st > 0; st >>= 1)
                s2 += __shfl_xor_sync(0xffffffffu, s2, st);
            if (lane == 0) red[0] = s2;
        }
        __syncthreads();
        const float inv = 1.f / red[0];
        #pragma unroll
        for (int i = 0; i < 8; i++) {
            float a = sa[tid + i*256] * inv;
            sa[tid + i*256] = a;
            if (b == 0) att0[tid + i*256] = a;
        }
    }
    __syncthreads();

    // ---- Phase 3: context. Warp strides 8; MLP=4, 4 accumulators.
    const float4* vbase = (const float4*)(hv + (size_t)b * (T_ * H_));
    float4 a0 = make_float4(0.f,0.f,0.f,0.f);
    float4 a1 = make_float4(0.f,0.f,0.f,0.f);
    float4 a2 = make_float4(0.f,0.f,0.f,0.f);
    float4 a3 = make_float4(0.f,0.f,0.f,0.f);
    for (int t = warp; t < T_; t += 32) {
        float w0 = sa[t], w1 = sa[t+8], w2 = sa[t+16], w3 = sa[t+24];
        float4 v0 = __ldcs(&vbase[(size_t)(t)    * 32 + lane]);
        float4 v1 = __ldcs(&vbase[(size_t)(t+8)  * 32 + lane]);
        float4 v2 = __ldcs(&vbase[(size_t)(t+16) * 32 + lane]);
        float4 v3 = __ldcs(&vbase[(size_t)(t+24) * 32 + lane]);
        a0.x = fmaf(w0, v0.x, a0.x); a0.y = fmaf(w0, v0.y, a0.y);
        a0.z = fmaf(w0, v0.z, a0.z); a0.w = fmaf(w0, v0.w, a0.w);
        a1.x = fmaf(w1, v1.x, a1.x); a1.y = fmaf(w1, v1.y, a1.y);
        a1.z = fmaf(w1, v1.z, a1.z); a1.w = fmaf(w1, v1.w, a1.w);
        a2.x = fmaf(w2, v2.x, a2.x); a2.y = fmaf(w2, v2.y, a2.y);
        a2.z = fmaf(w2, v2.z, a2.z); a2.w = fmaf(w2, v2.w, a2.w);
        a3.x = fmaf(w3, v3.x, a3.x); a3.y = fmaf(w3, v3.y, a3.y);
        a3.z = fmaf(w3, v3.z, a3.z); a3.w = fmaf(w3, v3.w, a3.w);
    }
    a0.x += a1.x + a2.x + a3.x;
    a0.y += a1.y + a2.y + a3.y;
    a0.z += a1.z + a2.z + a3.z;
    a0.w += a1.w + a2.w + a3.w;
    part[warp][lane] = a0;
    __syncthreads();
    if (warp == 0) {
        float4 s = part[0][lane];
        #pragma unroll
        for (int w = 1; w < 8; w++) {
            float4 p = part[w][lane];
            s.x += p.x; s.y += p.y; s.z += p.z; s.w += p.w;
        }
        ((float4*)(c_out + (size_t)b * H_))[lane] = s;
        cc[lane] = s;
    }
    __syncthreads();

    // ---- Phase 4: head row + BN-stat atomics.
    // pre[b][n] = q.W1[n] + c.W2[n] + b1[n] + b2[n]; accumulate sum/sumsq.
    {
        const float4 xq = sq[lane];
        const float4 xc = cc[lane];
        #pragma unroll
        for (int j = 0; j < 16; j++) {
            const int n = warp * 16 + j;
            float4 w1v = __ldg(((const float4*)(W1 + (size_t)n * H_)) + lane);
            float4 w2v = __ldg(((const float4*)(W2 + (size_t)n * H_)) + lane);
            float d = xq.x*w1v.x + xq.y*w1v.y + xq.z*w1v.z + xq.w*w1v.w
                    + xc.x*w2v.x + xc.y*w2v.y + xc.z*w2v.z + xc.w*w2v.w;
            #pragma unroll
            for (int st = 16; st > 0; st >>= 1)
                d += __shfl_xor_sync(0xffffffffu, d, st);
            if (lane == 0) {
                d += b1[n] + b2[n];
                g_pre[(size_t)b * H_ + n] = d;
                atomicAdd(&g_bnacc[n], d);
                atomicAdd(&g_bnacc[H_ + n], d * d);
            }
        }
    }
}

// ---------------------------------------------------------------------------
// BN apply + ReLU + final linear; mean/var computed inline from g_bnacc.
// ---------------------------------------------------------------------------
__global__ void k_final(const float* __restrict__ gamma, const float* __restrict__ beta,
                        const float* __restrict__ W3, const float* __restrict__ b3,
                        float* __restrict__ out) {
    int b = blockIdx.x, f = threadIdx.x;
    const int warp = f >> 5, lane = f & 31;
    __shared__ float sn[H_];
    float mn = g_bnacc[f] * (1.f / 512.f);
    float vr = g_bnacc[H_ + f] * (1.f / 512.f) - mn * mn;
    float v = g_pre[(size_t)b * H_ + f];
    float n = (v - mn) * rsqrtf(vr + 1e-5f) * gamma[f] + beta[f];
    sn[f] = fmaxf(n, 0.f);
    __syncthreads();
    float x0 = sn[lane], x1 = sn[lane + 32], x2 = sn[lane + 64], x3 = sn[lane + 96];
    for (int vo = warp; vo < V_; vo += 4) {
        const float* w = W3 + (size_t)vo * H_;
        float d = x0 * w[lane] + x1 * w[lane + 32] + x2 * w[lane + 64] + x3 * w[lane + 96];
        d += __shfl_xor_sync(0xffffffffu, d, 16);
        d += __shfl_xor_sync(0xffffffffu, d, 8);
        d += __shfl_xor_sync(0xffffffffu, d, 4);
        d += __shfl_xor_sync(0xffffffffu, d, 2);
        d += __shfl_xor_sync(0xffffffffu, d, 1);
        if (lane == 0) out[(size_t)b * V_ + vo] = d + b3[vo];
    }
}

// ---------------------------------------------------------------------------
extern "C" void kernel_launch(void* const* d_in, const int* in_sizes, int n_in,
                              void* d_out_v, int out_size) {
    const float* hk    = (const float*)d_in[0];
    const float* hv    = (const float*)d_in[1];
    const float* y_1   = (const float*)d_in[2];
    const float* c_1   = (const float*)d_in[3];
    const float* sh_1  = (const float*)d_in[4];   // [2,B,H]
    const float* sc_1  = (const float*)d_in[5];   // [2,B,H]
    const float* mask  = (const float*)d_in[6];
    const float* W_ih0 = (const float*)d_in[7];   // [512, 384]
    const float* W_hh0 = (const float*)d_in[8];   // [512, 128]
    const float* b_ih0 = (const float*)d_in[9];
    const float* b_hh0 = (const float*)d_in[10];
    const float* W_ih1 = (const float*)d_in[11];  // [512, 128]
    const float* W_hh1 = (const float*)d_in[12];  // [512, 128]
    const float* b_ih1 = (const float*)d_in[13];
    const float* b_hh1 = (const float*)d_in[14];
    const float* W1    = (const float*)d_in[15];  // [128, 128]
    const float* b1    = (const float*)d_in[16];
    const float* W2    = (const float*)d_in[17];  // [128, 128]
    const float* b2    = (const float*)d_in[18];
    const float* W3    = (const float*)d_in[19];  // [34, 128]
    const float* b3    = (const float*)d_in[20];
    const float* gamma = (const float*)d_in[21];
    const float* beta  = (const float*)d_in[22];
    float* d_out = (float*)d_out_v;
    (void)in_sizes; (void)n_in; (void)out_size;

    // LSTM cell 0: X = [y_1(256) | c_1(128) | sh_1[0](128)], Kin=384, K=512
    k_lstm<<<dim3(H_/16, B_/32), 512>>>(
        y_1, E_, c_1, H_, sh_1, H_,
        W_ih0, E_ + H_, W_hh0, b_ih0, b_hh0,
        sc_1, d_out + OFF_SH0, d_out + OFF_SC0, 0);

    // LSTM cell 1: X = [sh0(128) | sh_1[1](128)], Kin=128, K=256.
    // zero_acc=1: idle worker-1 threads of block (0,0) zero g_bnacc.
    k_lstm<<<dim3(H_/16, B_/32), 512>>>(
        d_out + OFF_SH0, H_, sh_1 + B_*H_, H_, (const float*)nullptr, 0,
        W_ih1, H_, W_hh1, b_ih1, b_hh1,
        sc_1 + B_*H_, d_out + OFF_SH1, d_out + OFF_SC1, 1);

    // Attention + head row + BN-stat atomics (256-thr blocks, 4 resident/SM)
    k_attn<<<B_, 256>>>(hk, hv, d_out + OFF_SH1, mask,
                        W1, W2, b1, b2,
                        d_out + OFF_C, d_out + OFF_ATT);

    // BN apply + final GEMV (stats computed inline from g_bnacc)
    k_final<<<B_, 128>>>(gamma, beta, W3, b3, d_out + OFF_OUT);
}

// round 14
// speedup vs baseline: 1.1022x; 1.1022x over previous
#include <cuda_runtime.h>
#include <math.h>

// Problem constants
#define B_ 512
#define T_ 2048
#define H_ 128
#define E_ 256
#define V_ 34

// Output layout: (out[B,V], c[B,H], sh0[B,H], sh1[B,H], sc0[B,H], sc1[B,H], atten_vec[T])
#define OFF_OUT 0
#define OFF_C   (B_*V_)
#define OFF_SH0 (OFF_C   + B_*H_)
#define OFF_SH1 (OFF_SH0 + B_*H_)
#define OFF_SC0 (OFF_SH1 + B_*H_)
#define OFF_SC1 (OFF_SC0 + B_*H_)
#define OFF_ATT (OFF_SC1 + B_*H_)

// Scratch (__device__ globals; no allocations allowed)
__device__ float g_pre[B_*H_];        // head pre-BN output
__device__ float g_bnpart[8][2*H_];   // per-rowgroup partial [sum | sumsq]

__device__ __forceinline__ float sigm(float x) { return 1.f / (1.f + __expf(-x)); }

// ---------------------------------------------------------------------------
// LSTM cell with in-block split-K on the proven 32-row tile. (R12, unchanged)
// ---------------------------------------------------------------------------
struct GemmBuf32 { float Xs[2][16][34]; float Ws[2][16][68]; };

__global__ void __launch_bounds__(512) k_lstm(
    const float* __restrict__ A, int ka,
    const float* __restrict__ Bp, int kb,
    const float* __restrict__ Cp, int kc,
    const float* __restrict__ Wih, int Kin,
    const float* __restrict__ Whh,
    const float* __restrict__ bih, const float* __restrict__ bhh,
    const float* __restrict__ c_prev,
    float* __restrict__ h_out, float* __restrict__ c_out)
{
    __shared__ GemmBuf32 gbuf[2];
    __shared__ float comb[256][8];
    const int tid = threadIdx.x;
    const int widx = tid >> 8;          // worker 0/1
    const int wtid = tid & 255;
    GemmBuf32& g = gbuf[widx];
    const int tx = wtid & 15, ty = wtid >> 4;
    const int m0 = blockIdx.y * 32;
    const int h0 = blockIdx.x * 16;
    const int lkk = wtid & 15, lr = wtid >> 4;

    const int K = ka + kb + kc;
    const int halfK = K >> 1;
    const int nt = halfK >> 4;
    const int kofs = widx * halfK;

    int wn[4];
    #pragma unroll
    for (int p = 0; p < 4; p++) {
        int c = lr + p * 16;
        wn[p] = (c & 3) * H_ + h0 + (c >> 2);   // gate*H + h
    }

    {
        int k = kofs + lkk;
        float x0, x1;
        if (k < ka)           { x0 = A[(m0+lr)*ka + k];            x1 = A[(m0+lr+16)*ka + k]; }
        else if (k < ka + kb) { x0 = Bp[(m0+lr)*kb + k - ka];      x1 = Bp[(m0+lr+16)*kb + k - ka]; }
        else                  { x0 = Cp[(m0+lr)*kc + k - ka - kb]; x1 = Cp[(m0+lr+16)*kc + k - ka - kb]; }
        g.Xs[0][lkk][lr] = x0; g.Xs[0][lkk][lr+16] = x1;
        #pragma unroll
        for (int p = 0; p < 4; p++)
            g.Ws[0][lkk][lr + p*16] = (k < Kin) ? Wih[wn[p]*Kin + k] : Whh[wn[p]*H_ + k - Kin];
    }
    __syncthreads();

    float acc[2][4] = {};
    for (int it = 0; it < nt; it++) {
        const int cur = it & 1, nxt = cur ^ 1;
        float px0 = 0.f, px1 = 0.f, pw[4] = {0.f,0.f,0.f,0.f};
        const bool more = (it + 1 < nt);
        if (more) {
            int k = kofs + (it + 1) * 16 + lkk;
            if (k < ka)           { px0 = A[(m0+lr)*ka + k];            px1 = A[(m0+lr+16)*ka + k]; }
            else if (k < ka + kb) { px0 = Bp[(m0+lr)*kb + k - ka];      px1 = Bp[(m0+lr+16)*kb + k - ka]; }
            else                  { px0 = Cp[(m0+lr)*kc + k - ka - kb]; px1 = Cp[(m0+lr+16)*kc + k - ka - kb]; }
            #pragma unroll
            for (int p = 0; p < 4; p++)
                pw[p] = (k < Kin) ? Wih[wn[p]*Kin + k] : Whh[wn[p]*H_ + k - Kin];
        }
        #pragma unroll
        for (int kk = 0; kk < 16; kk++) {
            float x0 = g.Xs[cur][kk][ty*2];
            float x1 = g.Xs[cur][kk][ty*2 + 1];
            float4 wv = *(const float4*)&g.Ws[cur][kk][tx*4];
            acc[0][0] = fmaf(x0, wv.x, acc[0][0]);
            acc[0][1] = fmaf(x0, wv.y, acc[0][1]);
            acc[0][2] = fmaf(x0, wv.z, acc[0][2]);
            acc[0][3] = fmaf(x0, wv.w, acc[0][3]);
            acc[1][0] = fmaf(x1, wv.x, acc[1][0]);
            acc[1][1] = fmaf(x1, wv.y, acc[1][1]);
            acc[1][2] = fmaf(x1, wv.z, acc[1][2]);
            acc[1][3] = fmaf(x1, wv.w, acc[1][3]);
        }
        if (more) {
            g.Xs[nxt][lkk][lr] = px0;
            g.Xs[nxt][lkk][lr+16] = px1;
            #pragma unroll
            for (int p = 0; p < 4; p++) g.Ws[nxt][lkk][lr + p*16] = pw[p];
            __syncthreads();
        }
    }

    if (widx == 1) {
        #pragma unroll
        for (int r = 0; r < 2; r++)
            #pragma unroll
            for (int j = 0; j < 4; j++) comb[wtid][r*4 + j] = acc[r][j];
    }
    __syncthreads();
    if (widx == 0) {
        const int h = h0 + tx;
        const float bi = bih[h]         + bhh[h];
        const float bf = bih[H_ + h]    + bhh[H_ + h];
        const float bg = bih[2*H_ + h]  + bhh[2*H_ + h];
        const float bo = bih[3*H_ + h]  + bhh[3*H_ + h];
        #pragma unroll
        for (int r = 0; r < 2; r++) {
            const int m = m0 + ty*2 + r;
            float a0 = acc[r][0] + comb[wtid][r*4 + 0];
            float a1 = acc[r][1] + comb[wtid][r*4 + 1];
            float a2 = acc[r][2] + comb[wtid][r*4 + 2];
            float a3 = acc[r][3] + comb[wtid][r*4 + 3];
            float ig = sigm(a0 + bi);
            float fg = sigm(a1 + bf);
            float gg = tanhf(a2 + bg);
            float og = sigm(a3 + bo);
            float cn = fg * c_prev[m*H_ + h] + ig * gg;
            c_out[m*H_ + h] = cn;
            h_out[m*H_ + h] = og * tanhf(cn);
        }
    }
}

// ---------------------------------------------------------------------------
// Fused attention + head, 256-thread blocks, 4 resident/SM. (R12, unchanged)
// ---------------------------------------------------------------------------
__global__ void __launch_bounds__(256, 4) k_attn(
    const float* __restrict__ hk, const float* __restrict__ hv,
    const float* __restrict__ q, const float* __restrict__ mask,
    const float* __restrict__ W1, const float* __restrict__ W2,
    const float* __restrict__ b1, const float* __restrict__ b2,
    float* __restrict__ c_out, float* __restrict__ att0)
{
    __shared__ float  sa[T_];
    __shared__ float4 sq[32];           // q row
    __shared__ float4 cc[32];           // c row
    __shared__ float4 part[8][32];
    __shared__ float  red[8];
    const int b = blockIdx.x, tid = threadIdx.x;
    const int warp = tid >> 5, lane = tid & 31;

    if (tid < 32) sq[tid] = ((const float4*)(q + (size_t)b * H_))[tid];
    __syncthreads();
    const float4 qv = sq[lane];

    // ---- Phase 1: scores. Warp w covers t in [w*256,(w+1)*256), MLP=8.
    const float4* kbase = (const float4*)(hk + (size_t)b * (T_ * H_));
    {
        const int tbeg = warp * 256;
        for (int t0 = tbeg; t0 < tbeg + 256; t0 += 8) {
            float4 v[8];
            #pragma unroll
            for (int j = 0; j < 8; j++)
                v[j] = __ldcs(&kbase[(size_t)(t0+j) * 32 + lane]);
            float d[8];
            #pragma unroll
            for (int j = 0; j < 8; j++)
                d[j] = v[j].x*qv.x + v[j].y*qv.y + v[j].z*qv.z + v[j].w*qv.w;
            #pragma unroll
            for (int st = 16; st > 0; st >>= 1) {
                #pragma unroll
                for (int j = 0; j < 8; j++)
                    d[j] += __shfl_xor_sync(0xffffffffu, d[j], st);
            }
            if (lane == 0) {
                #pragma unroll
                for (int j = 0; j < 8; j++) sa[t0+j] = d[j];
            }
        }
    }
    __syncthreads();

    // ---- Phase 2: masked renormalized softmax (smem-resident, low regs).
    {
        const float* mk = mask + (size_t)b * T_;
        float mx = -1e30f;
        #pragma unroll
        for (int i = 0; i < 8; i++) mx = fmaxf(mx, sa[tid + i*256]);
        #pragma unroll
        for (int st = 16; st > 0; st >>= 1)
            mx = fmaxf(mx, __shfl_xor_sync(0xffffffffu, mx, st));
        if (lane == 0) red[warp] = mx;
        __syncthreads();
        if (warp == 0) {
            float m2 = (lane < 8) ? red[lane] : -1e30f;
            #pragma unroll
            for (int st = 4; st > 0; st >>= 1)
                m2 = fmaxf(m2, __shfl_xor_sync(0xffffffffu, m2, st));
            if (lane == 0) red[0] = m2;
        }
        __syncthreads();
        mx = red[0];
        __syncthreads();

        float sum = 0.f;
        #pragma unroll
        for (int i = 0; i < 8; i++) {
            float e = __expf(sa[tid + i*256] - mx) * mk[tid + i*256];
            sa[tid + i*256] = e;
            sum += e;
        }
        #pragma unroll
        for (int st = 16; st > 0; st >>= 1)
            sum += __shfl_xor_sync(0xffffffffu, sum, st);
        if (lane == 0) red[warp] = sum;
        __syncthreads();
        if (warp == 0) {
            float s2 = (lane < 8) ? red[lane] : 0.f;
            #pragma unroll
            for (int st = 4; st > 0; st >>= 1)
                s2 += __shfl_xor_sync(0xffffffffu, s2, st);
            if (lane == 0) red[0] = s2;
        }
        __syncthreads();
        const float inv = 1.f / red[0];
        #pragma unroll
        for (int i = 0; i < 8; i++) {
            float a = sa[tid + i*256] * inv;
            sa[tid + i*256] = a;
            if (b == 0) att0[tid + i*256] = a;
        }
    }
    __syncthreads();

    // ---- Phase 3: context. Warp strides 8; MLP=4, 4 accumulators.
    const float4* vbase = (const float4*)(hv + (size_t)b * (T_ * H_));
    float4 a0 = make_float4(0.f,0.f,0.f,0.f);
    float4 a1 = make_float4(0.f,0.f,0.f,0.f);
    float4 a2 = make_float4(0.f,0.f,0.f,0.f);
    float4 a3 = make_float4(0.f,0.f,0.f,0.f);
    for (int t = warp; t < T_; t += 32) {
        float w0 = sa[t], w1 = sa[t+8], w2 = sa[t+16], w3 = sa[t+24];
        float4 v0 = __ldcs(&vbase[(size_t)(t)    * 32 + lane]);
        float4 v1 = __ldcs(&vbase[(size_t)(t+8)  * 32 + lane]);
        float4 v2 = __ldcs(&vbase[(size_t)(t+16) * 32 + lane]);
        float4 v3 = __ldcs(&vbase[(size_t)(t+24) * 32 + lane]);
        a0.x = fmaf(w0, v0.x, a0.x); a0.y = fmaf(w0, v0.y, a0.y);
        a0.z = fmaf(w0, v0.z, a0.z); a0.w = fmaf(w0, v0.w, a0.w);
        a1.x = fmaf(w1, v1.x, a1.x); a1.y = fmaf(w1, v1.y, a1.y);
        a1.z = fmaf(w1, v1.z, a1.z); a1.w = fmaf(w1, v1.w, a1.w);
        a2.x = fmaf(w2, v2.x, a2.x); a2.y = fmaf(w2, v2.y, a2.y);
        a2.z = fmaf(w2, v2.z, a2.z); a2.w = fmaf(w2, v2.w, a2.w);
        a3.x = fmaf(w3, v3.x, a3.x); a3.y = fmaf(w3, v3.y, a3.y);
        a3.z = fmaf(w3, v3.z, a3.z); a3.w = fmaf(w3, v3.w, a3.w);
    }
    a0.x += a1.x + a2.x + a3.x;
    a0.y += a1.y + a2.y + a3.y;
    a0.z += a1.z + a2.z + a3.z;
    a0.w += a1.w + a2.w + a3.w;
    part[warp][lane] = a0;
    __syncthreads();
    if (warp == 0) {
        float4 s = part[0][lane];
        #pragma unroll
        for (int w = 1; w < 8; w++) {
            float4 p = part[w][lane];
            s.x += p.x; s.y += p.y; s.z += p.z; s.w += p.w;
        }
        ((float4*)(c_out + (size_t)b * H_))[lane] = s;
        cc[lane] = s;
    }
    __syncthreads();

    // ---- Phase 4: head row. Warp w computes n = w*16 .. w*16+15.
    {
        const float4 xq = sq[lane];
        const float4 xc = cc[lane];
        #pragma unroll
        for (int j = 0; j < 16; j++) {
            const int n = warp * 16 + j;
            float4 w1v = __ldg(((const float4*)(W1 + (size_t)n * H_)) + lane);
            float4 w2v = __ldg(((const float4*)(W2 + (size_t)n * H_)) + lane);
            float d = xq.x*w1v.x + xq.y*w1v.y + xq.z*w1v.z + xq.w*w1v.w
                    + xc.x*w2v.x + xc.y*w2v.y + xc.z*w2v.z + xc.w*w2v.w;
            #pragma unroll
            for (int st = 16; st > 0; st >>= 1)
                d += __shfl_xor_sync(0xffffffffu, d, st);
            if (lane == 0)
                g_pre[(size_t)b * H_ + n] = d + b1[n] + b2[n];
        }
    }
}

// ---------------------------------------------------------------------------
// BN partial stats: grid (4 fgroups, 8 rowgroups) = 32 blocks x 512 thr.
// Coalesced (lane = feature) AND parallel. Partials to g_bnpart (no atomics,
// no zeroing: every slot written every run, deterministic).
// ---------------------------------------------------------------------------
__global__ void __launch_bounds__(512) k_bn(void) {
    const int fg = blockIdx.x;          // feature group: f0 = fg*32
    const int rg = blockIdx.y;          // row group: rows rg*64 .. rg*64+63
    const int tid = threadIdx.x;
    const int warp = tid >> 5, lane = tid & 31;
    const int f = fg * 32 + lane;
    float s = 0.f, q = 0.f;
    #pragma unroll
    for (int i = 0; i < 4; i++) {
        int r = rg * 64 + warp + i * 16;
        float v = g_pre[(size_t)r * H_ + f];
        s += v; q += v * v;
    }
    __shared__ float ss[16][32], qq[16][32];
    ss[warp][lane] = s;
    qq[warp][lane] = q;
    __syncthreads();
    if (tid < 32) {
        float S = 0.f, Q = 0.f;
        #pragma unroll
        for (int w = 0; w < 16; w++) { S += ss[w][tid]; Q += qq[w][tid]; }
        g_bnpart[rg][fg * 32 + tid]      = S;
        g_bnpart[rg][H_ + fg * 32 + tid] = Q;
    }
}

// ---------------------------------------------------------------------------
// BN apply + ReLU + final linear. Grid 128 blocks x 512 thr; each 128-thread
// group handles one batch row (4 rows/block). Stats folded from g_bnpart.
// ---------------------------------------------------------------------------
__global__ void __launch_bounds__(512) k_final(
    const float* __restrict__ gamma, const float* __restrict__ beta,
    const float* __restrict__ W3, const float* __restrict__ b3,
    float* __restrict__ out) {
    const int tid = threadIdx.x;
    const int grp = tid >> 7;            // 0..3
    const int f = tid & 127;
    const int b = blockIdx.x * 4 + grp;
    const int warp = (tid & 127) >> 5, lane = tid & 31;
    __shared__ float sn[4][H_];
    float S = 0.f, Q = 0.f;
    #pragma unroll
    for (int p = 0; p < 8; p++) { S += g_bnpart[p][f]; Q += g_bnpart[p][H_ + f]; }
    float mn = S * (1.f / 512.f);
    float vr = Q * (1.f / 512.f) - mn * mn;
    float v = g_pre[(size_t)b * H_ + f];
    float n = (v - mn) * rsqrtf(vr + 1e-5f) * gamma[f] + beta[f];
    sn[grp][f] = fmaxf(n, 0.f);
    __syncthreads();
    float x0 = sn[grp][lane], x1 = sn[grp][lane + 32];
    float x2 = sn[grp][lane + 64], x3 = sn[grp][lane + 96];
    for (int vo = warp; vo < V_; vo += 4) {
        const float* w = W3 + (size_t)vo * H_;
        float d = x0 * w[lane] + x1 * w[lane + 32] + x2 * w[lane + 64] + x3 * w[lane + 96];
        d += __shfl_xor_sync(0xffffffffu, d, 16);
        d += __shfl_xor_sync(0xffffffffu, d, 8);
        d += __shfl_xor_sync(0xffffffffu, d, 4);
        d += __shfl_xor_sync(0xffffffffu, d, 2);
        d += __shfl_xor_sync(0xffffffffu, d, 1);
        if (lane == 0) out[(size_t)b * V_ + vo] = d + b3[vo];
    }
}

// ---------------------------------------------------------------------------
extern "C" void kernel_launch(void* const* d_in, const int* in_sizes, int n_in,
                              void* d_out_v, int out_size) {
    const float* hk    = (const float*)d_in[0];
    const float* hv    = (const float*)d_in[1];
    const float* y_1   = (const float*)d_in[2];
    const float* c_1   = (const float*)d_in[3];
    const float* sh_1  = (const float*)d_in[4];   // [2,B,H]
    const float* sc_1  = (const float*)d_in[5];   // [2,B,H]
    const float* mask  = (const float*)d_in[6];
    const float* W_ih0 = (const float*)d_in[7];   // [512, 384]
    const float* W_hh0 = (const float*)d_in[8];   // [512, 128]
    const float* b_ih0 = (const float*)d_in[9];
    const float* b_hh0 = (const float*)d_in[10];
    const float* W_ih1 = (const float*)d_in[11];  // [512, 128]
    const float* W_hh1 = (const float*)d_in[12];  // [512, 128]
    const float* b_ih1 = (const float*)d_in[13];
    const float* b_hh1 = (const float*)d_in[14];
    const float* W1    = (const float*)d_in[15];  // [128, 128]
    const float* b1    = (const float*)d_in[16];
    const float* W2    = (const float*)d_in[17];  // [128, 128]
    const float* b2    = (const float*)d_in[18];
    const float* W3    = (const float*)d_in[19];  // [34, 128]
    const float* b3    = (const float*)d_in[20];
    const float* gamma = (const float*)d_in[21];
    const float* beta  = (const float*)d_in[22];
    float* d_out = (float*)d_out_v;
    (void)in_sizes; (void)n_in; (void)out_size;

    // LSTM cell 0: X = [y_1(256) | c_1(128) | sh_1[0](128)], Kin=384, K=512
    k_lstm<<<dim3(H_/16, B_/32), 512>>>(
        y_1, E_, c_1, H_, sh_1, H_,
        W_ih0, E_ + H_, W_hh0, b_ih0, b_hh0,
        sc_1, d_out + OFF_SH0, d_out + OFF_SC0);

    // LSTM cell 1: X = [sh0(128) | sh_1[1](128)], Kin=128, K=256
    k_lstm<<<dim3(H_/16, B_/32), 512>>>(
        d_out + OFF_SH0, H_, sh_1 + B_*H_, H_, (const float*)nullptr, 0,
        W_ih1, H_, W_hh1, b_ih1, b_hh1,
        sc_1 + B_*H_, d_out + OFF_SH1, d_out + OFF_SC1);

    // Attention + head row (256-thr blocks, 4 resident/SM)
    k_attn<<<B_, 256>>>(hk, hv, d_out + OFF_SH1, mask,
                        W1, W2, b1, b2,
                        d_out + OFF_C, d_out + OFF_ATT);

    // BN partial stats (parallel + coalesced) + final
    k_bn<<<dim3(4, 8), 512>>>();
    k_final<<<B_/4, 512>>>(gamma, beta, W3, b3, d_out + OFF_OUT);
}